// round 5
// baseline (speedup 1.0000x reference)
#include <cuda_runtime.h>
#include <math.h>
#include <stdint.h>

#define BB 2
#define NN 2048
#define DD 512
#define HH 8
#define DH 64
#define INNER 512
#define ROWS (BB*NN)            // 4096
#define BHN ((size_t)BB*HH*NN*DH)

// -------- scratch (device globals; no allocation allowed) --------
__device__ float g_xn[ROWS*DD];
__device__ float g_lin[3*ROWS*INNER];
__device__ float g_qkv[3*BB*HH*NN*DH];
__device__ float g_o[ROWS*INNER];

// ---------------- helpers ----------------
__device__ __forceinline__ uint32_t smem_u32(const void* p) {
    uint32_t a;
    asm("{ .reg .u64 t; cvta.to.shared.u64 t, %1; cvt.u32.u64 %0, t; }" : "=r"(a) : "l"(p));
    return a;
}
__device__ __forceinline__ void mma_tf32(float* c, const uint32_t* a, const uint32_t* b) {
    asm volatile(
        "mma.sync.aligned.m16n8k8.row.col.f32.tf32.tf32.f32 "
        "{%0,%1,%2,%3}, {%4,%5,%6,%7}, {%8,%9}, {%0,%1,%2,%3};"
        : "+f"(c[0]), "+f"(c[1]), "+f"(c[2]), "+f"(c[3])
        : "r"(a[0]), "r"(a[1]), "r"(a[2]), "r"(a[3]), "r"(b[0]), "r"(b[1]));
}
__device__ __forceinline__ uint32_t f2tf(float x) {
    uint32_t r;
    asm("cvt.rna.tf32.f32 %0, %1;" : "=r"(r) : "f"(x));
    return r;
}
__device__ __forceinline__ void tfsplit(float x, uint32_t& big, uint32_t& small) {
    big = f2tf(x);
    small = __float_as_uint(x - __uint_as_float(big));
}
#define CP_ASYNC16(dst, src) \
    asm volatile("cp.async.cg.shared.global [%0], [%1], 16;" :: "r"(dst), "l"(src) : "memory")
#define CP_COMMIT() asm volatile("cp.async.commit_group;" ::: "memory")
#define CP_WAIT(n)  asm volatile("cp.async.wait_group %0;" :: "n"(n) : "memory")

// ---------------- LayerNorm ----------------
__global__ void ln_kernel(const float* __restrict__ x,
                          const float* __restrict__ gamma,
                          const float* __restrict__ beta,
                          float* __restrict__ xn) {
    int row = blockIdx.x;
    const float* xr = x + (size_t)row * DD;
    float* outr = xn + (size_t)row * DD;
    int t = threadIdx.x;
    float v0 = xr[t], v1 = xr[t + 256];
    float s = v0 + v1;
    float sq = v0 * v0 + v1 * v1;
    #pragma unroll
    for (int o = 16; o > 0; o >>= 1) {
        s  += __shfl_xor_sync(0xffffffffu, s, o);
        sq += __shfl_xor_sync(0xffffffffu, sq, o);
    }
    __shared__ float ss[8], ssq[8];
    if ((t & 31) == 0) { ss[t >> 5] = s; ssq[t >> 5] = sq; }
    __syncthreads();
    s = 0.f; sq = 0.f;
    #pragma unroll
    for (int i = 0; i < 8; ++i) { s += ss[i]; sq += ssq[i]; }
    float mean = s * (1.f / DD);
    float var  = sq * (1.f / DD) - mean * mean;
    float rstd = rsqrtf(var + 1e-5f);
    outr[t]       = (v0 - mean) * rstd * gamma[t]       + beta[t];
    outr[t + 256] = (v1 - mean) * rstd * gamma[t + 256] + beta[t + 256];
}

// ---------------- 3xTF32 mma.sync GEMM (unchanged from R4) ----------------
#define GP 36
#define GCHUNK (128 * GP)
#define SM_GEMM (4 * GCHUNK * 4)

__global__ void __launch_bounds__(256)
gemm_mma(const float* __restrict__ A,
         const float* __restrict__ W0, const float* __restrict__ W1, const float* __restrict__ W2,
         float* __restrict__ C0, float* __restrict__ C1, float* __restrict__ C2,
         int NO, int K) {
    const float* W = (blockIdx.z == 0) ? W0 : (blockIdx.z == 1) ? W1 : W2;
    float*       C = (blockIdx.z == 0) ? C0 : (blockIdx.z == 1) ? C1 : C2;

    extern __shared__ float sm[];
    float* sA = sm;
    float* sW = sm + 2 * GCHUNK;

    int tid = threadIdx.x;
    int wid = tid >> 5, lane = tid & 31;
    int wm = wid >> 2, wn = wid & 3;
    int lq = lane >> 2, lm = lane & 3;
    int m0 = blockIdx.y * 128, e0 = blockIdx.x * 128;

    int lrow = tid >> 1;
    int lc4  = (tid & 1) << 2;
    const int nchunk = K >> 5;

    float acc[4][4][4];
    #pragma unroll
    for (int i = 0; i < 4; ++i)
        #pragma unroll
        for (int j = 0; j < 4; ++j)
            #pragma unroll
            for (int q = 0; q < 4; ++q) acc[i][j][q] = 0.f;

    uint32_t sAu = smem_u32(sA), sWu = smem_u32(sW);

    auto load_chunk = [&](int c, int buf) {
        int k0 = c << 5;
        const float* Ag = A + (size_t)(m0 + lrow) * K + k0 + lc4 * 4;
        const float* Wg = W + (size_t)(e0 + lrow) * K + k0 + lc4 * 4;
        uint32_t dstA = sAu + (uint32_t)(buf * GCHUNK + lrow * GP + lc4 * 4) * 4;
        uint32_t dstW = sWu + (uint32_t)(buf * GCHUNK + lrow * GP + lc4 * 4) * 4;
        #pragma unroll
        for (int i = 0; i < 4; ++i) {
            CP_ASYNC16(dstA + i * 16, Ag + i * 4);
            CP_ASYNC16(dstW + i * 16, Wg + i * 4);
        }
    };

    load_chunk(0, 0);
    CP_COMMIT();

    for (int c = 0; c < nchunk; ++c) {
        if (c + 1 < nchunk) {
            load_chunk(c + 1, (c + 1) & 1);
            CP_COMMIT();
            CP_WAIT(1);
        } else {
            CP_WAIT(0);
        }
        __syncthreads();
        const float* sAb = sA + (c & 1) * GCHUNK;
        const float* sWb = sW + (c & 1) * GCHUNK;
        #pragma unroll
        for (int k4 = 0; k4 < 4; ++k4) {
            int kc = k4 * 8;
            uint32_t ab[4][4], as_[4][4], bb[4][2], bs[4][2];
            #pragma unroll
            for (int mt = 0; mt < 4; ++mt) {
                int r = wm * 64 + mt * 16 + lq;
                tfsplit(sAb[r * GP + kc + lm],           ab[mt][0], as_[mt][0]);
                tfsplit(sAb[(r + 8) * GP + kc + lm],     ab[mt][1], as_[mt][1]);
                tfsplit(sAb[r * GP + kc + lm + 4],       ab[mt][2], as_[mt][2]);
                tfsplit(sAb[(r + 8) * GP + kc + lm + 4], ab[mt][3], as_[mt][3]);
            }
            #pragma unroll
            for (int nt = 0; nt < 4; ++nt) {
                int n = wn * 32 + nt * 8 + lq;
                tfsplit(sWb[n * GP + kc + lm],     bb[nt][0], bs[nt][0]);
                tfsplit(sWb[n * GP + kc + lm + 4], bb[nt][1], bs[nt][1]);
            }
            #pragma unroll
            for (int mt = 0; mt < 4; ++mt)
                #pragma unroll
                for (int nt = 0; nt < 4; ++nt) {
                    mma_tf32(acc[mt][nt], ab[mt],  bb[nt]);
                    mma_tf32(acc[mt][nt], as_[mt], bb[nt]);
                    mma_tf32(acc[mt][nt], ab[mt],  bs[nt]);
                }
        }
        __syncthreads();
    }

    #pragma unroll
    for (int mt = 0; mt < 4; ++mt) {
        int r0 = m0 + wm * 64 + mt * 16 + lq;
        #pragma unroll
        for (int nt = 0; nt < 4; ++nt) {
            int c0 = e0 + wn * 32 + nt * 8 + lm * 2;
            *(float2*)(C + (size_t)r0 * NO + c0)       = make_float2(acc[mt][nt][0], acc[mt][nt][1]);
            *(float2*)(C + (size_t)(r0 + 8) * NO + c0) = make_float2(acc[mt][nt][2], acc[mt][nt][3]);
        }
    }
}

// ------- depthwise causal conv (k=3) + head split + q scale -------
__global__ void conv_split_kernel(const float* __restrict__ lin,
                                  const float* __restrict__ wqd,
                                  const float* __restrict__ wkd,
                                  const float* __restrict__ wvd,
                                  float* __restrict__ qkv) {
    int idx = blockIdx.x * 256 + threadIdx.x;
    int e = idx & (INNER - 1);
    int n = (idx >> 9) & (NN - 1);
    int b = idx >> 20;
    int h = e >> 6, d = e & 63;
    size_t dst = (((size_t)(b * HH + h) * NN + n) * DH + d);
    #pragma unroll
    for (int t = 0; t < 3; ++t) {
        const float* L = lin + (size_t)t * ROWS * INNER;
        const float* wd = (t == 0) ? wqd : (t == 1) ? wkd : wvd;
        float y2 = L[idx];
        float y1 = (n >= 1) ? L[idx - INNER] : 0.f;
        float y0 = (n >= 2) ? L[idx - 2 * INNER] : 0.f;
        float v = wd[e * 3 + 0] * y0 + wd[e * 3 + 1] * y1 + wd[e * 3 + 2] * y2;
        if (t == 0) v *= 0.125f;
        qkv[(size_t)t * BHN + dst] = v;
    }
}

// ---------------- Flash attention, pre-split 3xTF32 ----------------
// Br=128, Bc=64, 256 threads (8 warps, 16 rows each).
// Q/K/V pre-split into big/small smem tiles (split once, not per warp).
// S = 3 mma passes; P stored as rna-tf32, PV = 2 passes (P single, V split).
#define AP 68
// smem float offsets
#define O_QB 0
#define O_QS (128 * AP)
#define O_KB (2 * 128 * AP)
#define O_KS (O_KB + 64 * AP)
#define O_VB (O_KS + 64 * AP)
#define O_VS (O_VB + 64 * AP)
#define O_P  (O_VS + 64 * AP)
#define SMEM_ATTN ((O_P + 128 * AP) * 4)    // 174080 bytes

__global__ void __launch_bounds__(256, 1)
attn_kernel(const float* __restrict__ qkv, float* __restrict__ o) {
    extern __shared__ float smf[];
    float* Qb = smf + O_QB;
    float* Qs = smf + O_QS;
    float* Kb = smf + O_KB;
    float* Ks = smf + O_KS;
    float* Vb = smf + O_VB;
    float* Vs = smf + O_VS;
    float* Pt = smf + O_P;

    int qt = gridDim.x - 1 - blockIdx.x;   // big tiles first
    int bh = blockIdx.y;
    int b = bh >> 3, h = bh & 7;
    int qs = qt * 128;
    const float* qb = qkv + (size_t)bh * NN * DH;
    const float* kb = qkv + BHN + (size_t)bh * NN * DH;
    const float* vb = qkv + 2 * BHN + (size_t)bh * NN * DH;

    int tid = threadIdx.x;
    int wid = tid >> 5, lane = tid & 31;
    int lq = lane >> 2, lm = lane & 3;
    int wr = wid * 16;

    // load + split Q tile (128 rows): 8 float4 per thread
    #pragma unroll
    for (int i = 0; i < 8; ++i) {
        int idx = i * 256 + tid;
        int rr = idx >> 4, c4 = idx & 15;
        float4 v = *(const float4*)(qb + (size_t)(qs + rr) * DH + c4 * 4);
        uint32_t bx, sx, by, sy, bz, sz, bw, sw;
        tfsplit(v.x, bx, sx); tfsplit(v.y, by, sy);
        tfsplit(v.z, bz, sz); tfsplit(v.w, bw, sw);
        int off = rr * AP + c4 * 4;
        *(uint4*)(Qb + off) = make_uint4(bx, by, bz, bw);
        *(uint4*)(Qs + off) = make_uint4(sx, sy, sz, sw);
    }

    float acc_o[8][4];
    #pragma unroll
    for (int nt = 0; nt < 8; ++nt)
        #pragma unroll
        for (int q = 0; q < 4; ++q) acc_o[nt][q] = 0.f;
    float m0r = -1e30f, m1r = -1e30f, l0r = 0.f, l1r = 0.f;
    float slope = exp2f(-(float)(h + 1));
    int ig0 = qs + wr + lq, ig1 = ig0 + 8;

    __syncthreads();
    int ntile = 2 * qt + 2;
    for (int t = 0; t < ntile; ++t) {
        int ks0 = t * 64;
        // load + split K and V tiles: 4 float4 each per thread
        #pragma unroll
        for (int i = 0; i < 4; ++i) {
            int idx = i * 256 + tid;
            int rr = idx >> 4, c4 = idx & 15;
            int off = rr * AP + c4 * 4;
            float4 kv = *(const float4*)(kb + (size_t)(ks0 + rr) * DH + c4 * 4);
            float4 vv = *(const float4*)(vb + (size_t)(ks0 + rr) * DH + c4 * 4);
            uint32_t bx, sx, by, sy, bz, sz, bw, sw;
            tfsplit(kv.x, bx, sx); tfsplit(kv.y, by, sy);
            tfsplit(kv.z, bz, sz); tfsplit(kv.w, bw, sw);
            *(uint4*)(Kb + off) = make_uint4(bx, by, bz, bw);
            *(uint4*)(Ks + off) = make_uint4(sx, sy, sz, sw);
            tfsplit(vv.x, bx, sx); tfsplit(vv.y, by, sy);
            tfsplit(vv.z, bz, sz); tfsplit(vv.w, bw, sw);
            *(uint4*)(Vb + off) = make_uint4(bx, by, bz, bw);
            *(uint4*)(Vs + off) = make_uint4(sx, sy, sz, sw);
        }
        __syncthreads();

        bool active = (ks0 <= qs + wr + 15);   // slab not fully masked
        if (active) {
            // S = Q K^T, 3 passes from pre-split tiles
            float acc_s[8][4];
            #pragma unroll
            for (int nt = 0; nt < 8; ++nt)
                #pragma unroll
                for (int q = 0; q < 4; ++q) acc_s[nt][q] = 0.f;
            #pragma unroll
            for (int ks = 0; ks < 8; ++ks) {
                int kc = ks * 8;
                uint32_t ab[4], as_[4];
                int ra = (wr + lq) * AP + kc + lm;
                ab[0]  = __float_as_uint(Qb[ra]);
                as_[0] = __float_as_uint(Qs[ra]);
                ab[1]  = __float_as_uint(Qb[ra + 8 * AP]);
                as_[1] = __float_as_uint(Qs[ra + 8 * AP]);
                ab[2]  = __float_as_uint(Qb[ra + 4]);
                as_[2] = __float_as_uint(Qs[ra + 4]);
                ab[3]  = __float_as_uint(Qb[ra + 8 * AP + 4]);
                as_[3] = __float_as_uint(Qs[ra + 8 * AP + 4]);
                #pragma unroll
                for (int nt = 0; nt < 8; ++nt) {
                    int rb = (nt * 8 + lq) * AP + kc + lm;
                    uint32_t bb[2], bs[2];
                    bb[0] = __float_as_uint(Kb[rb]);
                    bs[0] = __float_as_uint(Ks[rb]);
                    bb[1] = __float_as_uint(Kb[rb + 4]);
                    bs[1] = __float_as_uint(Ks[rb + 4]);
                    mma_tf32(acc_s[nt], ab,  bb);
                    mma_tf32(acc_s[nt], as_, bb);
                    mma_tf32(acc_s[nt], ab,  bs);
                }
            }

            // bias + causal mask
            #pragma unroll
            for (int nt = 0; nt < 8; ++nt) {
                int jg = ks0 + nt * 8 + lm * 2;
                acc_s[nt][0] = (jg     <= ig0) ? acc_s[nt][0] - slope * (float)(ig0 - jg)     : -1e30f;
                acc_s[nt][1] = (jg + 1 <= ig0) ? acc_s[nt][1] - slope * (float)(ig0 - jg - 1) : -1e30f;
                acc_s[nt][2] = (jg     <= ig1) ? acc_s[nt][2] - slope * (float)(ig1 - jg)     : -1e30f;
                acc_s[nt][3] = (jg + 1 <= ig1) ? acc_s[nt][3] - slope * (float)(ig1 - jg - 1) : -1e30f;
            }

            // online softmax (quad reduce)
            float rm0 = -1e30f, rm1 = -1e30f;
            #pragma unroll
            for (int nt = 0; nt < 8; ++nt) {
                rm0 = fmaxf(rm0, fmaxf(acc_s[nt][0], acc_s[nt][1]));
                rm1 = fmaxf(rm1, fmaxf(acc_s[nt][2], acc_s[nt][3]));
            }
            rm0 = fmaxf(rm0, __shfl_xor_sync(0xffffffffu, rm0, 1));
            rm0 = fmaxf(rm0, __shfl_xor_sync(0xffffffffu, rm0, 2));
            rm1 = fmaxf(rm1, __shfl_xor_sync(0xffffffffu, rm1, 1));
            rm1 = fmaxf(rm1, __shfl_xor_sync(0xffffffffu, rm1, 2));
            float mn0 = fmaxf(m0r, rm0), mn1 = fmaxf(m1r, rm1);
            float al0 = __expf(m0r - mn0), al1 = __expf(m1r - mn1);
            float ls0 = 0.f, ls1 = 0.f;
            #pragma unroll
            for (int nt = 0; nt < 8; ++nt) {
                acc_s[nt][0] = __expf(acc_s[nt][0] - mn0);
                acc_s[nt][1] = __expf(acc_s[nt][1] - mn0);
                acc_s[nt][2] = __expf(acc_s[nt][2] - mn1);
                acc_s[nt][3] = __expf(acc_s[nt][3] - mn1);
                ls0 += acc_s[nt][0] + acc_s[nt][1];
                ls1 += acc_s[nt][2] + acc_s[nt][3];
            }
            ls0 += __shfl_xor_sync(0xffffffffu, ls0, 1);
            ls0 += __shfl_xor_sync(0xffffffffu, ls0, 2);
            ls1 += __shfl_xor_sync(0xffffffffu, ls1, 1);
            ls1 += __shfl_xor_sync(0xffffffffu, ls1, 2);
            l0r = l0r * al0 + ls0;  m0r = mn0;
            l1r = l1r * al1 + ls1;  m1r = mn1;
            #pragma unroll
            for (int nt = 0; nt < 8; ++nt) {
                acc_o[nt][0] *= al0; acc_o[nt][1] *= al0;
                acc_o[nt][2] *= al1; acc_o[nt][3] *= al1;
            }

            // stash P as rna-rounded tf32 (single precision pass in PV)
            #pragma unroll
            for (int nt = 0; nt < 8; ++nt) {
                int cc = nt * 8 + lm * 2;
                uint2 p0 = make_uint2(f2tf(acc_s[nt][0]), f2tf(acc_s[nt][1]));
                uint2 p1 = make_uint2(f2tf(acc_s[nt][2]), f2tf(acc_s[nt][3]));
                *(uint2*)(Pt + (wr + lq) * AP + cc)     = p0;
                *(uint2*)(Pt + (wr + lq + 8) * AP + cc) = p1;
            }
            __syncwarp();

            // O += P @ V : 2 passes (P single, V split)
            #pragma unroll
            for (int ks = 0; ks < 8; ++ks) {
                int kc = ks * 8;
                uint32_t a[4];
                int ra = (wr + lq) * AP + kc + lm;
                a[0] = __float_as_uint(Pt[ra]);
                a[1] = __float_as_uint(Pt[ra + 8 * AP]);
                a[2] = __float_as_uint(Pt[ra + 4]);
                a[3] = __float_as_uint(Pt[ra + 8 * AP + 4]);
                #pragma unroll
                for (int nt = 0; nt < 8; ++nt) {
                    int rb0 = (kc + lm) * AP + nt * 8 + lq;
                    uint32_t bb[2], bs[2];
                    bb[0] = __float_as_uint(Vb[rb0]);
                    bs[0] = __float_as_uint(Vs[rb0]);
                    bb[1] = __float_as_uint(Vb[rb0 + 4 * AP]);
                    bs[1] = __float_as_uint(Vs[rb0 + 4 * AP]);
                    mma_tf32(acc_o[nt], a, bb);
                    mma_tf32(acc_o[nt], a, bs);
                }
            }
        }
        __syncthreads();
    }

    float inv0 = 1.f / l0r, inv1 = 1.f / l1r;
    int n0 = qs + wr + lq, n1 = n0 + 8;
    #pragma unroll
    for (int nt = 0; nt < 8; ++nt) {
        int cc = h * DH + nt * 8 + lm * 2;
        *(float2*)(o + ((size_t)b * NN + n0) * INNER + cc) =
            make_float2(acc_o[nt][0] * inv0, acc_o[nt][1] * inv0);
        *(float2*)(o + ((size_t)b * NN + n1) * INNER + cc) =
            make_float2(acc_o[nt][2] * inv1, acc_o[nt][3] * inv1);
    }
}

extern "C" void kernel_launch(void* const* d_in, const int* in_sizes, int n_in,
                              void* d_out, int out_size) {
    const float* x     = (const float*)d_in[0];
    const float* gamma = (const float*)d_in[1];
    const float* beta  = (const float*)d_in[2];
    const float* wq1   = (const float*)d_in[3];
    const float* wqd   = (const float*)d_in[4];
    const float* wk1   = (const float*)d_in[5];
    const float* wkd   = (const float*)d_in[6];
    const float* wv1   = (const float*)d_in[7];
    const float* wvd   = (const float*)d_in[8];
    const float* wout  = (const float*)d_in[9];
    float* out = (float*)d_out;

    float *xn, *lin, *qkv, *o;
    cudaGetSymbolAddress((void**)&xn,  g_xn);
    cudaGetSymbolAddress((void**)&lin, g_lin);
    cudaGetSymbolAddress((void**)&qkv, g_qkv);
    cudaGetSymbolAddress((void**)&o,   g_o);

    cudaFuncSetAttribute(gemm_mma, cudaFuncAttributeMaxDynamicSharedMemorySize, SM_GEMM);
    cudaFuncSetAttribute(attn_kernel, cudaFuncAttributeMaxDynamicSharedMemorySize, SMEM_ATTN);

    ln_kernel<<<ROWS, 256>>>(x, gamma, beta, xn);

    dim3 g1(INNER / 128, ROWS / 128, 3);
    gemm_mma<<<g1, 256, SM_GEMM>>>(xn, wq1, wk1, wv1,
                                   lin, lin + (size_t)ROWS * INNER, lin + 2 * (size_t)ROWS * INNER,
                                   INNER, DD);

    conv_split_kernel<<<(ROWS * INNER) / 256, 256>>>(lin, wqd, wkd, wvd, qkv);

    attn_kernel<<<dim3(NN / 128, BB * HH), 256, SMEM_ATTN>>>(qkv, o);

    dim3 g2(DD / 128, ROWS / 128, 1);
    gemm_mma<<<g2, 256, SM_GEMM>>>(o, wout, wout, wout, out, out, out, DD, INNER);
}

// round 6
// speedup vs baseline: 1.2834x; 1.2834x over previous
#include <cuda_runtime.h>
#include <math.h>
#include <stdint.h>

#define BB 2
#define NN 2048
#define DD 512
#define HH 8
#define DH 64
#define INNER 512
#define ROWS (BB*NN)            // 4096
#define BHN ((size_t)BB*HH*NN*DH)

// -------- scratch (device globals; no allocation allowed) --------
__device__ float g_xn[ROWS*DD];
__device__ float g_lin[3*ROWS*INNER];
__device__ float g_qkv[3*BB*HH*NN*DH];
__device__ float g_o[ROWS*INNER];

// ---------------- helpers ----------------
__device__ __forceinline__ uint32_t smem_u32(const void* p) {
    uint32_t a;
    asm("{ .reg .u64 t; cvta.to.shared.u64 t, %1; cvt.u32.u64 %0, t; }" : "=r"(a) : "l"(p));
    return a;
}
__device__ __forceinline__ void mma_tf32(float* c, const uint32_t* a, const uint32_t* b) {
    asm volatile(
        "mma.sync.aligned.m16n8k8.row.col.f32.tf32.tf32.f32 "
        "{%0,%1,%2,%3}, {%4,%5,%6,%7}, {%8,%9}, {%0,%1,%2,%3};"
        : "+f"(c[0]), "+f"(c[1]), "+f"(c[2]), "+f"(c[3])
        : "r"(a[0]), "r"(a[1]), "r"(a[2]), "r"(a[3]), "r"(b[0]), "r"(b[1]));
}
__device__ __forceinline__ uint32_t f2tf(float x) {
    uint32_t r;
    asm("cvt.rna.tf32.f32 %0, %1;" : "=r"(r) : "f"(x));
    return r;
}
__device__ __forceinline__ void tfsplit(float x, uint32_t& big, uint32_t& small) {
    big = f2tf(x);
    small = __float_as_uint(x - __uint_as_float(big));
}
#define CP_ASYNC16(dst, src) \
    asm volatile("cp.async.cg.shared.global [%0], [%1], 16;" :: "r"(dst), "l"(src) : "memory")
#define CP_COMMIT() asm volatile("cp.async.commit_group;" ::: "memory")
#define CP_WAIT(n)  asm volatile("cp.async.wait_group %0;" :: "n"(n) : "memory")

// ---------------- LayerNorm ----------------
__global__ void ln_kernel(const float* __restrict__ x,
                          const float* __restrict__ gamma,
                          const float* __restrict__ beta,
                          float* __restrict__ xn) {
    int row = blockIdx.x;
    const float* xr = x + (size_t)row * DD;
    float* outr = xn + (size_t)row * DD;
    int t = threadIdx.x;
    float v0 = xr[t], v1 = xr[t + 256];
    float s = v0 + v1;
    float sq = v0 * v0 + v1 * v1;
    #pragma unroll
    for (int o = 16; o > 0; o >>= 1) {
        s  += __shfl_xor_sync(0xffffffffu, s, o);
        sq += __shfl_xor_sync(0xffffffffu, sq, o);
    }
    __shared__ float ss[8], ssq[8];
    if ((t & 31) == 0) { ss[t >> 5] = s; ssq[t >> 5] = sq; }
    __syncthreads();
    s = 0.f; sq = 0.f;
    #pragma unroll
    for (int i = 0; i < 8; ++i) { s += ss[i]; sq += ssq[i]; }
    float mean = s * (1.f / DD);
    float var  = sq * (1.f / DD) - mean * mean;
    float rstd = rsqrtf(var + 1e-5f);
    outr[t]       = (v0 - mean) * rstd * gamma[t]       + beta[t];
    outr[t + 256] = (v1 - mean) * rstd * gamma[t + 256] + beta[t + 256];
}

// ---------------- 3xTF32 mma.sync GEMM (unchanged) ----------------
#define GP 36
#define GCHUNK (128 * GP)
#define SM_GEMM (4 * GCHUNK * 4)

__global__ void __launch_bounds__(256)
gemm_mma(const float* __restrict__ A,
         const float* __restrict__ W0, const float* __restrict__ W1, const float* __restrict__ W2,
         float* __restrict__ C0, float* __restrict__ C1, float* __restrict__ C2,
         int NO, int K) {
    const float* W = (blockIdx.z == 0) ? W0 : (blockIdx.z == 1) ? W1 : W2;
    float*       C = (blockIdx.z == 0) ? C0 : (blockIdx.z == 1) ? C1 : C2;

    extern __shared__ float sm[];
    float* sA = sm;
    float* sW = sm + 2 * GCHUNK;

    int tid = threadIdx.x;
    int wid = tid >> 5, lane = tid & 31;
    int wm = wid >> 2, wn = wid & 3;
    int lq = lane >> 2, lm = lane & 3;
    int m0 = blockIdx.y * 128, e0 = blockIdx.x * 128;

    int lrow = tid >> 1;
    int lc4  = (tid & 1) << 2;
    const int nchunk = K >> 5;

    float acc[4][4][4];
    #pragma unroll
    for (int i = 0; i < 4; ++i)
        #pragma unroll
        for (int j = 0; j < 4; ++j)
            #pragma unroll
            for (int q = 0; q < 4; ++q) acc[i][j][q] = 0.f;

    uint32_t sAu = smem_u32(sA), sWu = smem_u32(sW);

    auto load_chunk = [&](int c, int buf) {
        int k0 = c << 5;
        const float* Ag = A + (size_t)(m0 + lrow) * K + k0 + lc4 * 4;
        const float* Wg = W + (size_t)(e0 + lrow) * K + k0 + lc4 * 4;
        uint32_t dstA = sAu + (uint32_t)(buf * GCHUNK + lrow * GP + lc4 * 4) * 4;
        uint32_t dstW = sWu + (uint32_t)(buf * GCHUNK + lrow * GP + lc4 * 4) * 4;
        #pragma unroll
        for (int i = 0; i < 4; ++i) {
            CP_ASYNC16(dstA + i * 16, Ag + i * 4);
            CP_ASYNC16(dstW + i * 16, Wg + i * 4);
        }
    };

    load_chunk(0, 0);
    CP_COMMIT();

    for (int c = 0; c < nchunk; ++c) {
        if (c + 1 < nchunk) {
            load_chunk(c + 1, (c + 1) & 1);
            CP_COMMIT();
            CP_WAIT(1);
        } else {
            CP_WAIT(0);
        }
        __syncthreads();
        const float* sAb = sA + (c & 1) * GCHUNK;
        const float* sWb = sW + (c & 1) * GCHUNK;
        #pragma unroll
        for (int k4 = 0; k4 < 4; ++k4) {
            int kc = k4 * 8;
            uint32_t ab[4][4], as_[4][4], bb[4][2], bs[4][2];
            #pragma unroll
            for (int mt = 0; mt < 4; ++mt) {
                int r = wm * 64 + mt * 16 + lq;
                tfsplit(sAb[r * GP + kc + lm],           ab[mt][0], as_[mt][0]);
                tfsplit(sAb[(r + 8) * GP + kc + lm],     ab[mt][1], as_[mt][1]);
                tfsplit(sAb[r * GP + kc + lm + 4],       ab[mt][2], as_[mt][2]);
                tfsplit(sAb[(r + 8) * GP + kc + lm + 4], ab[mt][3], as_[mt][3]);
            }
            #pragma unroll
            for (int nt = 0; nt < 4; ++nt) {
                int n = wn * 32 + nt * 8 + lq;
                tfsplit(sWb[n * GP + kc + lm],     bb[nt][0], bs[nt][0]);
                tfsplit(sWb[n * GP + kc + lm + 4], bb[nt][1], bs[nt][1]);
            }
            #pragma unroll
            for (int mt = 0; mt < 4; ++mt)
                #pragma unroll
                for (int nt = 0; nt < 4; ++nt) {
                    mma_tf32(acc[mt][nt], ab[mt],  bb[nt]);
                    mma_tf32(acc[mt][nt], as_[mt], bb[nt]);
                    mma_tf32(acc[mt][nt], ab[mt],  bs[nt]);
                }
        }
        __syncthreads();
    }

    #pragma unroll
    for (int mt = 0; mt < 4; ++mt) {
        int r0 = m0 + wm * 64 + mt * 16 + lq;
        #pragma unroll
        for (int nt = 0; nt < 4; ++nt) {
            int c0 = e0 + wn * 32 + nt * 8 + lm * 2;
            *(float2*)(C + (size_t)r0 * NO + c0)       = make_float2(acc[mt][nt][0], acc[mt][nt][1]);
            *(float2*)(C + (size_t)(r0 + 8) * NO + c0) = make_float2(acc[mt][nt][2], acc[mt][nt][3]);
        }
    }
}

// ------- depthwise causal conv (k=3) + head split + q scale -------
__global__ void conv_split_kernel(const float* __restrict__ lin,
                                  const float* __restrict__ wqd,
                                  const float* __restrict__ wkd,
                                  const float* __restrict__ wvd,
                                  float* __restrict__ qkv) {
    int idx = blockIdx.x * 256 + threadIdx.x;
    int e = idx & (INNER - 1);
    int n = (idx >> 9) & (NN - 1);
    int b = idx >> 20;
    int h = e >> 6, d = e & 63;
    size_t dst = (((size_t)(b * HH + h) * NN + n) * DH + d);
    #pragma unroll
    for (int t = 0; t < 3; ++t) {
        const float* L = lin + (size_t)t * ROWS * INNER;
        const float* wd = (t == 0) ? wqd : (t == 1) ? wkd : wvd;
        float y2 = L[idx];
        float y1 = (n >= 1) ? L[idx - INNER] : 0.f;
        float y0 = (n >= 2) ? L[idx - 2 * INNER] : 0.f;
        float v = wd[e * 3 + 0] * y0 + wd[e * 3 + 1] * y1 + wd[e * 3 + 2] * y2;
        if (t == 0) v *= 0.125f;
        qkv[(size_t)t * BHN + dst] = v;
    }
}

// ---------------- Flash attention ----------------
// Br=Bc=64, 128 threads (4 warps x 16 rows).
// K cooperatively pre-split into Kb/Ks; V rounded to tf32 (Vt); Q raw
// fragments in registers, split per k-step. S = 3 mma passes,
// PV = 1 pass (P stored rna-tf32). 4 smem buffers -> 3 blocks/SM.
#define AP 68
#define O_KB 0
#define O_KS (64 * AP)
#define O_VT (2 * 64 * AP)
#define O_P  (3 * 64 * AP)
#define SMEM_ATTN (4 * 64 * AP * 4)     // 69632 bytes

__global__ void __launch_bounds__(128, 3)
attn_kernel(const float* __restrict__ qkv, float* __restrict__ o) {
    extern __shared__ float smf[];
    float* Kb = smf + O_KB;
    float* Ks = smf + O_KS;
    float* Vt = smf + O_VT;
    float* Pt = smf + O_P;

    int qt = gridDim.x - 1 - blockIdx.x;   // big tiles first
    int bh = blockIdx.y;
    int b = bh >> 3, h = bh & 7;
    int qs = qt * 64;
    const float* qb = qkv + (size_t)bh * NN * DH;
    const float* kb = qkv + BHN + (size_t)bh * NN * DH;
    const float* vb = qkv + 2 * BHN + (size_t)bh * NN * DH;

    int tid = threadIdx.x;
    int wid = tid >> 5, lane = tid & 31;
    int lq = lane >> 2, lm = lane & 3;
    int wr = wid * 16;

    // stage Q into Pt, then lift raw fragments into registers
    #pragma unroll
    for (int i = 0; i < 8; ++i) {
        int idx = i * 128 + tid;
        int rr = idx >> 4, c4 = idx & 15;
        *(float4*)(Pt + rr * AP + c4 * 4) = *(const float4*)(qb + (size_t)(qs + rr) * DH + c4 * 4);
    }
    __syncthreads();
    float qraw[8][4];
    #pragma unroll
    for (int ks = 0; ks < 8; ++ks) {
        int ra = (wr + lq) * AP + ks * 8 + lm;
        qraw[ks][0] = Pt[ra];
        qraw[ks][1] = Pt[ra + 8 * AP];
        qraw[ks][2] = Pt[ra + 4];
        qraw[ks][3] = Pt[ra + 8 * AP + 4];
    }
    __syncthreads();

    float acc_o[8][4];
    #pragma unroll
    for (int nt = 0; nt < 8; ++nt)
        #pragma unroll
        for (int q = 0; q < 4; ++q) acc_o[nt][q] = 0.f;
    float m0r = -1e30f, m1r = -1e30f, l0r = 0.f, l1r = 0.f;
    float slope = exp2f(-(float)(h + 1));
    int ig0 = qs + wr + lq, ig1 = ig0 + 8;

    int ntile = qt + 1;
    for (int t = 0; t < ntile; ++t) {
        int ks0 = t * 64;
        // cooperative load: K split into big/small, V rounded to tf32
        #pragma unroll
        for (int i = 0; i < 8; ++i) {
            int idx = i * 128 + tid;
            int rr = idx >> 4, c4 = idx & 15;
            int off = rr * AP + c4 * 4;
            float4 kv = *(const float4*)(kb + (size_t)(ks0 + rr) * DH + c4 * 4);
            float4 vv = *(const float4*)(vb + (size_t)(ks0 + rr) * DH + c4 * 4);
            uint32_t bx, sx, by, sy, bz, sz, bw, sw;
            tfsplit(kv.x, bx, sx); tfsplit(kv.y, by, sy);
            tfsplit(kv.z, bz, sz); tfsplit(kv.w, bw, sw);
            *(uint4*)(Kb + off) = make_uint4(bx, by, bz, bw);
            *(uint4*)(Ks + off) = make_uint4(sx, sy, sz, sw);
            *(uint4*)(Vt + off) = make_uint4(f2tf(vv.x), f2tf(vv.y), f2tf(vv.z), f2tf(vv.w));
        }
        __syncthreads();

        // S = Q K^T, 3 passes (Q split on the fly from registers)
        float acc_s[8][4];
        #pragma unroll
        for (int nt = 0; nt < 8; ++nt)
            #pragma unroll
            for (int q = 0; q < 4; ++q) acc_s[nt][q] = 0.f;
        #pragma unroll
        for (int ks = 0; ks < 8; ++ks) {
            int kc = ks * 8;
            uint32_t ab[4], as_[4];
            tfsplit(qraw[ks][0], ab[0], as_[0]);
            tfsplit(qraw[ks][1], ab[1], as_[1]);
            tfsplit(qraw[ks][2], ab[2], as_[2]);
            tfsplit(qraw[ks][3], ab[3], as_[3]);
            #pragma unroll
            for (int nt = 0; nt < 8; ++nt) {
                int rb = (nt * 8 + lq) * AP + kc + lm;
                uint32_t bb[2], bs[2];
                bb[0] = __float_as_uint(Kb[rb]);
                bs[0] = __float_as_uint(Ks[rb]);
                bb[1] = __float_as_uint(Kb[rb + 4]);
                bs[1] = __float_as_uint(Ks[rb + 4]);
                mma_tf32(acc_s[nt], ab,  bb);
                mma_tf32(acc_s[nt], as_, bb);
                mma_tf32(acc_s[nt], ab,  bs);
            }
        }

        // bias + causal mask
        #pragma unroll
        for (int nt = 0; nt < 8; ++nt) {
            int jg = ks0 + nt * 8 + lm * 2;
            acc_s[nt][0] = (jg     <= ig0) ? acc_s[nt][0] - slope * (float)(ig0 - jg)     : -1e30f;
            acc_s[nt][1] = (jg + 1 <= ig0) ? acc_s[nt][1] - slope * (float)(ig0 - jg - 1) : -1e30f;
            acc_s[nt][2] = (jg     <= ig1) ? acc_s[nt][2] - slope * (float)(ig1 - jg)     : -1e30f;
            acc_s[nt][3] = (jg + 1 <= ig1) ? acc_s[nt][3] - slope * (float)(ig1 - jg - 1) : -1e30f;
        }

        // online softmax (quad reduce)
        float rm0 = -1e30f, rm1 = -1e30f;
        #pragma unroll
        for (int nt = 0; nt < 8; ++nt) {
            rm0 = fmaxf(rm0, fmaxf(acc_s[nt][0], acc_s[nt][1]));
            rm1 = fmaxf(rm1, fmaxf(acc_s[nt][2], acc_s[nt][3]));
        }
        rm0 = fmaxf(rm0, __shfl_xor_sync(0xffffffffu, rm0, 1));
        rm0 = fmaxf(rm0, __shfl_xor_sync(0xffffffffu, rm0, 2));
        rm1 = fmaxf(rm1, __shfl_xor_sync(0xffffffffu, rm1, 1));
        rm1 = fmaxf(rm1, __shfl_xor_sync(0xffffffffu, rm1, 2));
        float mn0 = fmaxf(m0r, rm0), mn1 = fmaxf(m1r, rm1);
        float al0 = __expf(m0r - mn0), al1 = __expf(m1r - mn1);
        float ls0 = 0.f, ls1 = 0.f;
        #pragma unroll
        for (int nt = 0; nt < 8; ++nt) {
            acc_s[nt][0] = __expf(acc_s[nt][0] - mn0);
            acc_s[nt][1] = __expf(acc_s[nt][1] - mn0);
            acc_s[nt][2] = __expf(acc_s[nt][2] - mn1);
            acc_s[nt][3] = __expf(acc_s[nt][3] - mn1);
            ls0 += acc_s[nt][0] + acc_s[nt][1];
            ls1 += acc_s[nt][2] + acc_s[nt][3];
        }
        ls0 += __shfl_xor_sync(0xffffffffu, ls0, 1);
        ls0 += __shfl_xor_sync(0xffffffffu, ls0, 2);
        ls1 += __shfl_xor_sync(0xffffffffu, ls1, 1);
        ls1 += __shfl_xor_sync(0xffffffffu, ls1, 2);
        l0r = l0r * al0 + ls0;  m0r = mn0;
        l1r = l1r * al1 + ls1;  m1r = mn1;
        #pragma unroll
        for (int nt = 0; nt < 8; ++nt) {
            acc_o[nt][0] *= al0; acc_o[nt][1] *= al0;
            acc_o[nt][2] *= al1; acc_o[nt][3] *= al1;
        }

        // stash P as rna-tf32 (each warp writes/reads its own 16 rows)
        #pragma unroll
        for (int nt = 0; nt < 8; ++nt) {
            int cc = nt * 8 + lm * 2;
            *(uint2*)(Pt + (wr + lq) * AP + cc) =
                make_uint2(f2tf(acc_s[nt][0]), f2tf(acc_s[nt][1]));
            *(uint2*)(Pt + (wr + lq + 8) * AP + cc) =
                make_uint2(f2tf(acc_s[nt][2]), f2tf(acc_s[nt][3]));
        }
        __syncwarp();

        // O += P @ V : single pass (both operands tf32-rounded)
        #pragma unroll
        for (int ks = 0; ks < 8; ++ks) {
            int kc = ks * 8;
            uint32_t a[4];
            int ra = (wr + lq) * AP + kc + lm;
            a[0] = __float_as_uint(Pt[ra]);
            a[1] = __float_as_uint(Pt[ra + 8 * AP]);
            a[2] = __float_as_uint(Pt[ra + 4]);
            a[3] = __float_as_uint(Pt[ra + 8 * AP + 4]);
            #pragma unroll
            for (int nt = 0; nt < 8; ++nt) {
                int rb0 = (kc + lm) * AP + nt * 8 + lq;
                uint32_t bb[2];
                bb[0] = __float_as_uint(Vt[rb0]);
                bb[1] = __float_as_uint(Vt[rb0 + 4 * AP]);
                mma_tf32(acc_o[nt], a, bb);
            }
        }
        __syncthreads();
    }

    float inv0 = 1.f / l0r, inv1 = 1.f / l1r;
    int n0 = qs + wr + lq, n1 = n0 + 8;
    #pragma unroll
    for (int nt = 0; nt < 8; ++nt) {
        int cc = h * DH + nt * 8 + lm * 2;
        *(float2*)(o + ((size_t)b * NN + n0) * INNER + cc) =
            make_float2(acc_o[nt][0] * inv0, acc_o[nt][1] * inv0);
        *(float2*)(o + ((size_t)b * NN + n1) * INNER + cc) =
            make_float2(acc_o[nt][2] * inv1, acc_o[nt][3] * inv1);
    }
}

extern "C" void kernel_launch(void* const* d_in, const int* in_sizes, int n_in,
                              void* d_out, int out_size) {
    const float* x     = (const float*)d_in[0];
    const float* gamma = (const float*)d_in[1];
    const float* beta  = (const float*)d_in[2];
    const float* wq1   = (const float*)d_in[3];
    const float* wqd   = (const float*)d_in[4];
    const float* wk1   = (const float*)d_in[5];
    const float* wkd   = (const float*)d_in[6];
    const float* wv1   = (const float*)d_in[7];
    const float* wvd   = (const float*)d_in[8];
    const float* wout  = (const float*)d_in[9];
    float* out = (float*)d_out;

    float *xn, *lin, *qkv, *o;
    cudaGetSymbolAddress((void**)&xn,  g_xn);
    cudaGetSymbolAddress((void**)&lin, g_lin);
    cudaGetSymbolAddress((void**)&qkv, g_qkv);
    cudaGetSymbolAddress((void**)&o,   g_o);

    cudaFuncSetAttribute(gemm_mma, cudaFuncAttributeMaxDynamicSharedMemorySize, SM_GEMM);
    cudaFuncSetAttribute(attn_kernel, cudaFuncAttributeMaxDynamicSharedMemorySize, SMEM_ATTN);

    ln_kernel<<<ROWS, 256>>>(x, gamma, beta, xn);

    dim3 g1(INNER / 128, ROWS / 128, 3);
    gemm_mma<<<g1, 256, SM_GEMM>>>(xn, wq1, wk1, wv1,
                                   lin, lin + (size_t)ROWS * INNER, lin + 2 * (size_t)ROWS * INNER,
                                   INNER, DD);

    conv_split_kernel<<<(ROWS * INNER) / 256, 256>>>(lin, wqd, wkd, wvd, qkv);

    attn_kernel<<<dim3(NN / 64, BB * HH), 128, SMEM_ATTN>>>(qkv, o);

    dim3 g2(DD / 128, ROWS / 128, 1);
    gemm_mma<<<g2, 256, SM_GEMM>>>(o, wout, wout, wout, out, out, out, DD, INNER);
}

// round 7
// speedup vs baseline: 1.8128x; 1.4124x over previous
#include <cuda_runtime.h>
#include <cuda_bf16.h>
#include <math.h>
#include <stdint.h>

#define BB 2
#define NN 2048
#define DD 512
#define HH 8
#define DH 64
#define INNER 512
#define ROWS (BB*NN)            // 4096
#define BHN ((size_t)BB*HH*NN*DH)
#define WSZ (INNER*DD)          // 262144 = 2^18

// -------- scratch (device globals; no allocation allowed) --------
__device__ float g_lin[3*ROWS*INNER];          // pointwise-conv outputs (fp32)
__device__ __nv_bfloat16 g_xnb[ROWS*DD];       // LN out, big
__device__ __nv_bfloat16 g_xns[ROWS*DD];       // LN out, small
__device__ __nv_bfloat16 g_wb[4*WSZ];          // wq1,wk1,wv1,wout big
__device__ __nv_bfloat16 g_ws[4*WSZ];          // small
__device__ __nv_bfloat16 g_qb[BHN], g_qs[BHN]; // q split, [b][h][n][d]
__device__ __nv_bfloat16 g_kb[BHN], g_ks[BHN]; // k split, [b][h][n][d]
__device__ __nv_bfloat16 g_vbT[BHN], g_vsT[BHN]; // v split, TRANSPOSED [b][h][d][n]
__device__ __nv_bfloat16 g_ob[ROWS*INNER], g_os[ROWS*INNER]; // attn out split

// ---------------- helpers ----------------
__device__ __forceinline__ uint32_t smem_u32(const void* p) {
    uint32_t a;
    asm("{ .reg .u64 t; cvta.to.shared.u64 t, %1; cvt.u32.u64 %0, t; }" : "=r"(a) : "l"(p));
    return a;
}
__device__ __forceinline__ void mma_bf16(float* c, const uint32_t* a, const uint32_t* b) {
    asm volatile(
        "mma.sync.aligned.m16n8k16.row.col.f32.bf16.bf16.f32 "
        "{%0,%1,%2,%3}, {%4,%5,%6,%7}, {%8,%9}, {%0,%1,%2,%3};"
        : "+f"(c[0]), "+f"(c[1]), "+f"(c[2]), "+f"(c[3])
        : "r"(a[0]), "r"(a[1]), "r"(a[2]), "r"(a[3]), "r"(b[0]), "r"(b[1]));
}
__device__ __forceinline__ void split1(float x, __nv_bfloat16& b, __nv_bfloat16& s) {
    b = __float2bfloat16(x);
    s = __float2bfloat16(x - __bfloat162float(b));
}
__device__ __forceinline__ void split2(float x0, float x1, uint32_t& b, uint32_t& s) {
    __nv_bfloat162 tb = __float22bfloat162_rn(make_float2(x0, x1));
    float2 tf = __bfloat1622float2(tb);
    __nv_bfloat162 ts = __float22bfloat162_rn(make_float2(x0 - tf.x, x1 - tf.y));
    b = *reinterpret_cast<uint32_t*>(&tb);
    s = *reinterpret_cast<uint32_t*>(&ts);
}
#define CP_ASYNC16(dst, src) \
    asm volatile("cp.async.cg.shared.global [%0], [%1], 16;" :: "r"(dst), "l"(src) : "memory")
#define CP_COMMIT() asm volatile("cp.async.commit_group;" ::: "memory")
#define CP_WAIT(n)  asm volatile("cp.async.wait_group %0;" :: "n"(n) : "memory")

// ---------------- LayerNorm -> split bf16 ----------------
__global__ void ln_kernel(const float* __restrict__ x,
                          const float* __restrict__ gamma,
                          const float* __restrict__ beta,
                          __nv_bfloat16* __restrict__ xnb,
                          __nv_bfloat16* __restrict__ xns) {
    int row = blockIdx.x;
    const float* xr = x + (size_t)row * DD;
    int t = threadIdx.x;
    float v0 = xr[t], v1 = xr[t + 256];
    float s = v0 + v1;
    float sq = v0 * v0 + v1 * v1;
    #pragma unroll
    for (int o = 16; o > 0; o >>= 1) {
        s  += __shfl_xor_sync(0xffffffffu, s, o);
        sq += __shfl_xor_sync(0xffffffffu, sq, o);
    }
    __shared__ float ss[8], ssq[8];
    if ((t & 31) == 0) { ss[t >> 5] = s; ssq[t >> 5] = sq; }
    __syncthreads();
    s = 0.f; sq = 0.f;
    #pragma unroll
    for (int i = 0; i < 8; ++i) { s += ss[i]; sq += ssq[i]; }
    float mean = s * (1.f / DD);
    float var  = sq * (1.f / DD) - mean * mean;
    float rstd = rsqrtf(var + 1e-5f);
    float y0 = (v0 - mean) * rstd * gamma[t]       + beta[t];
    float y1 = (v1 - mean) * rstd * gamma[t + 256] + beta[t + 256];
    __nv_bfloat16 b, sm;
    split1(y0, b, sm); xnb[(size_t)row * DD + t] = b;       xns[(size_t)row * DD + t] = sm;
    split1(y1, b, sm); xnb[(size_t)row * DD + t + 256] = b; xns[(size_t)row * DD + t + 256] = sm;
}

// ---------------- weight split (4 matrices -> g_wb/g_ws) ----------------
__global__ void wsplit_kernel(const float* __restrict__ wq1, const float* __restrict__ wk1,
                              const float* __restrict__ wv1, const float* __restrict__ wout,
                              __nv_bfloat16* __restrict__ wb, __nv_bfloat16* __restrict__ ws) {
    int idx = blockIdx.x * 256 + threadIdx.x;       // 0 .. 4*WSZ-1
    int sel = idx >> 18;
    int off = idx & (WSZ - 1);
    const float* src = (sel == 0) ? wq1 : (sel == 1) ? wk1 : (sel == 2) ? wv1 : wout;
    __nv_bfloat16 b, s;
    split1(src[off], b, s);
    wb[idx] = b; ws[idx] = s;
}

// ---------------- bf16x3 mma.sync GEMM ----------------
// C[m][e] = sum_k A[m][k]*W[e][k], M=4096(K/NO=512). Tile 128x128, 8 warps
// (64x32), k-chunk 32, double-buffered cp.async, operands pre-split bf16.
#define GW 20                               // u32 row stride (16 data + 4 pad)
#define GTB (128 * GW * 4)                  // bytes per tile array (10240)
#define SM_GEMM (2 * 4 * GTB)               // 81920 bytes

__global__ void __launch_bounds__(256)
gemm_bf16(const __nv_bfloat16* __restrict__ Abig, const __nv_bfloat16* __restrict__ Asml,
          const __nv_bfloat16* __restrict__ wb,   const __nv_bfloat16* __restrict__ ws,
          size_t w_stride, float* __restrict__ Cbase, size_t c_stride) {
    const __nv_bfloat16* Wb = wb + blockIdx.z * w_stride;
    const __nv_bfloat16* Ws = ws + blockIdx.z * w_stride;
    float* C = Cbase + blockIdx.z * c_stride;

    extern __shared__ char smc[];
    uint32_t smb = smem_u32(smc);
    // buffer p: Ab, As, Wb, Ws tiles
    int tid = threadIdx.x;
    int wid = tid >> 5, lane = tid & 31;
    int wm = wid >> 2, wn = wid & 3;
    int lq = lane >> 2, lm = lane & 3;
    int m0 = blockIdx.y * 128, e0 = blockIdx.x * 128;

    int lrow = tid >> 1;                    // 0..127
    int lc2  = (tid & 1) * 2;               // 16B chunk base (0 or 2)

    float acc[4][4][4];
    #pragma unroll
    for (int i = 0; i < 4; ++i)
        #pragma unroll
        for (int j = 0; j < 4; ++j)
            #pragma unroll
            for (int q = 0; q < 4; ++q) acc[i][j][q] = 0.f;

    auto load_chunk = [&](int c, int buf) {
        int k0 = c << 5;
        uint32_t base = smb + buf * 4 * GTB;
        const __nv_bfloat16* a0 = Abig + (size_t)(m0 + lrow) * 512 + k0;
        const __nv_bfloat16* a1 = Asml + (size_t)(m0 + lrow) * 512 + k0;
        const __nv_bfloat16* w0 = Wb + (size_t)(e0 + lrow) * 512 + k0;
        const __nv_bfloat16* w1 = Ws + (size_t)(e0 + lrow) * 512 + k0;
        #pragma unroll
        for (int j = 0; j < 2; ++j) {
            int c4 = lc2 + j;                    // 16B chunk index 0..3
            uint32_t doff = (uint32_t)(lrow * GW + c4 * 4) * 4;
            CP_ASYNC16(base + doff,             a0 + c4 * 8);
            CP_ASYNC16(base + GTB + doff,       a1 + c4 * 8);
            CP_ASYNC16(base + 2 * GTB + doff,   w0 + c4 * 8);
            CP_ASYNC16(base + 3 * GTB + doff,   w1 + c4 * 8);
        }
    };

    load_chunk(0, 0);
    CP_COMMIT();

    const uint32_t* smu = (const uint32_t*)smc;
    for (int c = 0; c < 16; ++c) {
        if (c + 1 < 16) {
            load_chunk(c + 1, (c + 1) & 1);
            CP_COMMIT();
            CP_WAIT(1);
        } else {
            CP_WAIT(0);
        }
        __syncthreads();
        const uint32_t* Abu = smu + (c & 1) * 4 * (GTB / 4);
        const uint32_t* Asu = Abu + GTB / 4;
        const uint32_t* Wbu = Abu + 2 * (GTB / 4);
        const uint32_t* Wsu = Abu + 3 * (GTB / 4);
        #pragma unroll
        for (int ks = 0; ks < 2; ++ks) {
            int kb = ks * 8;
            uint32_t ab[4][4], as_[4][4], bb[4][2], bs[4][2];
            #pragma unroll
            for (int mt = 0; mt < 4; ++mt) {
                int r = wm * 64 + mt * 16 + lq;
                ab[mt][0] = Abu[r * GW + kb + lm];
                ab[mt][1] = Abu[(r + 8) * GW + kb + lm];
                ab[mt][2] = Abu[r * GW + kb + lm + 4];
                ab[mt][3] = Abu[(r + 8) * GW + kb + lm + 4];
                as_[mt][0] = Asu[r * GW + kb + lm];
                as_[mt][1] = Asu[(r + 8) * GW + kb + lm];
                as_[mt][2] = Asu[r * GW + kb + lm + 4];
                as_[mt][3] = Asu[(r + 8) * GW + kb + lm + 4];
            }
            #pragma unroll
            for (int nt = 0; nt < 4; ++nt) {
                int n = wn * 32 + nt * 8 + lq;
                bb[nt][0] = Wbu[n * GW + kb + lm];
                bb[nt][1] = Wbu[n * GW + kb + lm + 4];
                bs[nt][0] = Wsu[n * GW + kb + lm];
                bs[nt][1] = Wsu[n * GW + kb + lm + 4];
            }
            #pragma unroll
            for (int mt = 0; mt < 4; ++mt)
                #pragma unroll
                for (int nt = 0; nt < 4; ++nt) {
                    mma_bf16(acc[mt][nt], ab[mt],  bb[nt]);
                    mma_bf16(acc[mt][nt], as_[mt], bb[nt]);
                    mma_bf16(acc[mt][nt], ab[mt],  bs[nt]);
                }
        }
        __syncthreads();
    }

    #pragma unroll
    for (int mt = 0; mt < 4; ++mt) {
        int r0 = m0 + wm * 64 + mt * 16 + lq;
        #pragma unroll
        for (int nt = 0; nt < 4; ++nt) {
            int c0 = e0 + wn * 32 + nt * 8 + lm * 2;
            *(float2*)(C + (size_t)r0 * 512 + c0)       = make_float2(acc[mt][nt][0], acc[mt][nt][1]);
            *(float2*)(C + (size_t)(r0 + 8) * 512 + c0) = make_float2(acc[mt][nt][2], acc[mt][nt][3]);
        }
    }
}

// ------- depthwise conv for q,k + head split + q scale + bf16 split -------
__global__ void conv_qk(const float* __restrict__ lin,
                        const float* __restrict__ wqd, const float* __restrict__ wkd,
                        __nv_bfloat16* __restrict__ qb, __nv_bfloat16* __restrict__ qs,
                        __nv_bfloat16* __restrict__ kb, __nv_bfloat16* __restrict__ ks) {
    int idx = blockIdx.x * 256 + threadIdx.x;
    int e = idx & (INNER - 1);
    int n = (idx >> 9) & (NN - 1);
    int b = idx >> 20;
    int h = e >> 6, d = e & 63;
    size_t dst = (((size_t)(b * HH + h) * NN + n) * DH + d);
    #pragma unroll
    for (int t = 0; t < 2; ++t) {
        const float* L = lin + (size_t)t * ROWS * INNER;
        const float* wd = t ? wkd : wqd;
        float y2 = L[idx];
        float y1 = (n >= 1) ? L[idx - INNER] : 0.f;
        float y0 = (n >= 2) ? L[idx - 2 * INNER] : 0.f;
        float v = wd[e * 3 + 0] * y0 + wd[e * 3 + 1] * y1 + wd[e * 3 + 2] * y2;
        if (t == 0) v *= 0.125f;
        __nv_bfloat16 big, sml;
        split1(v, big, sml);
        if (t == 0) { qb[dst] = big; qs[dst] = sml; }
        else        { kb[dst] = big; ks[dst] = sml; }
    }
}

// ------- depthwise conv for v + TRANSPOSED split output -------
// grid (64 n-tiles, 16 e-tiles, B); block 256. smem-transpose for coalescing.
__global__ void conv_v(const float* __restrict__ lin2, const float* __restrict__ wvd,
                       __nv_bfloat16* __restrict__ vbT, __nv_bfloat16* __restrict__ vsT) {
    __shared__ float tile[34 * 33];
    int b = blockIdx.z, e0 = blockIdx.y * 32, n0 = blockIdx.x * 32;
    int tid = threadIdx.x;
    for (int i = tid; i < 34 * 32; i += 256) {
        int r = i >> 5, c = i & 31;
        int n = n0 - 2 + r;
        tile[r * 33 + c] = (n >= 0) ? lin2[((size_t)b * NN + n) * INNER + e0 + c] : 0.f;
    }
    __syncthreads();
    int nl = tid & 31;
    #pragma unroll
    for (int p = 0; p < 4; ++p) {
        int el = (tid >> 5) + p * 8;
        int eg = e0 + el;
        int h = eg >> 6, d = eg & 63;
        float y0 = tile[nl * 33 + el];
        float y1 = tile[(nl + 1) * 33 + el];
        float y2 = tile[(nl + 2) * 33 + el];
        float v = wvd[eg * 3 + 0] * y0 + wvd[eg * 3 + 1] * y1 + wvd[eg * 3 + 2] * y2;
        __nv_bfloat16 big, sml;
        split1(v, big, sml);
        size_t dst = ((size_t)(b * HH + h) * DH + d) * NN + n0 + nl;
        vbT[dst] = big; vsT[dst] = sml;
    }
}

// ---------------- Flash attention, bf16x3 mma ----------------
// Br=Bc=64, 128 threads (4 warps x 16 rows). All operands pre-split bf16.
// S: QbKb+QsKb+QbKs (3 passes). PV: PbVb+PsVb+PbVs (3 passes). k16 steps.
#define AW 36                               // u32 row stride
#define SMEM_ATTN (6 * 64 * AW * 4)         // Kb,Ks,Vb,Vs,Pb,Ps = 55296 B

__global__ void __launch_bounds__(128, 3)
attn_kernel(const __nv_bfloat16* __restrict__ qb_g, const __nv_bfloat16* __restrict__ qs_g,
            const __nv_bfloat16* __restrict__ kb_g, const __nv_bfloat16* __restrict__ ks_g,
            const __nv_bfloat16* __restrict__ vbT_g, const __nv_bfloat16* __restrict__ vsT_g,
            __nv_bfloat16* __restrict__ ob_g, __nv_bfloat16* __restrict__ os_g) {
    extern __shared__ uint32_t smu[];
    uint32_t* Kb = smu;
    uint32_t* Ks = smu + 64 * AW;
    uint32_t* Vb = smu + 2 * 64 * AW;
    uint32_t* Vs = smu + 3 * 64 * AW;
    uint32_t* Pb = smu + 4 * 64 * AW;
    uint32_t* Ps = smu + 5 * 64 * AW;
    uint32_t smb = smem_u32(smu);

    int qt = gridDim.x - 1 - blockIdx.x;   // big tiles first
    int bh = blockIdx.y;
    int b = bh >> 3, h = bh & 7;
    int qs0 = qt * 64;

    int tid = threadIdx.x;
    int wid = tid >> 5, lane = tid & 31;
    int lq = lane >> 2, lm = lane & 3;
    int wr = wid * 16;

    // Q fragments direct from global (packed u32 = 2 bf16 over d)
    const uint32_t* qbu = (const uint32_t*)qb_g + (size_t)bh * NN * 32;
    const uint32_t* qsu = (const uint32_t*)qs_g + (size_t)bh * NN * 32;
    int r0 = qs0 + wr + lq;
    uint32_t qbf[4][4], qsf[4][4];
    #pragma unroll
    for (int ks = 0; ks < 4; ++ks) {
        qbf[ks][0] = qbu[(size_t)r0 * 32 + ks * 8 + lm];
        qbf[ks][1] = qbu[(size_t)(r0 + 8) * 32 + ks * 8 + lm];
        qbf[ks][2] = qbu[(size_t)r0 * 32 + ks * 8 + lm + 4];
        qbf[ks][3] = qbu[(size_t)(r0 + 8) * 32 + ks * 8 + lm + 4];
        qsf[ks][0] = qsu[(size_t)r0 * 32 + ks * 8 + lm];
        qsf[ks][1] = qsu[(size_t)(r0 + 8) * 32 + ks * 8 + lm];
        qsf[ks][2] = qsu[(size_t)r0 * 32 + ks * 8 + lm + 4];
        qsf[ks][3] = qsu[(size_t)(r0 + 8) * 32 + ks * 8 + lm + 4];
    }

    float acc_o[8][4];
    #pragma unroll
    for (int nt = 0; nt < 8; ++nt)
        #pragma unroll
        for (int q = 0; q < 4; ++q) acc_o[nt][q] = 0.f;
    float m0r = -1e30f, m1r = -1e30f, l0r = 0.f, l1r = 0.f;
    float slope = exp2f(-(float)(h + 1));
    int ig0 = r0, ig1 = r0 + 8;

    const char* kbp = (const char*)(kb_g + (size_t)bh * NN * DH);
    const char* ksp = (const char*)(ks_g + (size_t)bh * NN * DH);
    const char* vbp = (const char*)(vbT_g + (size_t)bh * DH * NN);
    const char* vsp = (const char*)(vsT_g + (size_t)bh * DH * NN);

    int ntile = qt + 1;
    for (int t = 0; t < ntile; ++t) {
        int ks0 = t * 64;
        // cooperative cp.async: K/V big+small tiles (pre-split, packed bf16)
        #pragma unroll
        for (int i = 0; i < 4; ++i) {
            int idx = i * 128 + tid;
            int r = idx >> 3, c = idx & 7;
            uint32_t doff = (uint32_t)(r * AW + c * 4) * 4;
            CP_ASYNC16(smb + doff,                 kbp + (size_t)(ks0 + r) * 128 + c * 16);
            CP_ASYNC16(smb + 64 * AW * 4 + doff,   ksp + (size_t)(ks0 + r) * 128 + c * 16);
            CP_ASYNC16(smb + 2 * 64 * AW * 4 + doff, vbp + (size_t)r * (NN * 2) + ks0 * 2 + c * 16);
            CP_ASYNC16(smb + 3 * 64 * AW * 4 + doff, vsp + (size_t)r * (NN * 2) + ks0 * 2 + c * 16);
        }
        CP_COMMIT();
        CP_WAIT(0);
        __syncthreads();

        // S = Q K^T (bf16x3, 4 k16-steps)
        float acc_s[8][4];
        #pragma unroll
        for (int nt = 0; nt < 8; ++nt)
            #pragma unroll
            for (int q = 0; q < 4; ++q) acc_s[nt][q] = 0.f;
        #pragma unroll
        for (int ks = 0; ks < 4; ++ks) {
            int kc = ks * 8;
            #pragma unroll
            for (int nt = 0; nt < 8; ++nt) {
                int rb = (nt * 8 + lq) * AW + kc + lm;
                uint32_t bb[2], bs[2];
                bb[0] = Kb[rb];     bb[1] = Kb[rb + 4];
                bs[0] = Ks[rb];     bs[1] = Ks[rb + 4];
                mma_bf16(acc_s[nt], qbf[ks], bb);
                mma_bf16(acc_s[nt], qsf[ks], bb);
                mma_bf16(acc_s[nt], qbf[ks], bs);
            }
        }

        // bias + causal mask
        #pragma unroll
        for (int nt = 0; nt < 8; ++nt) {
            int jg = ks0 + nt * 8 + lm * 2;
            acc_s[nt][0] = (jg     <= ig0) ? acc_s[nt][0] - slope * (float)(ig0 - jg)     : -1e30f;
            acc_s[nt][1] = (jg + 1 <= ig0) ? acc_s[nt][1] - slope * (float)(ig0 - jg - 1) : -1e30f;
            acc_s[nt][2] = (jg     <= ig1) ? acc_s[nt][2] - slope * (float)(ig1 - jg)     : -1e30f;
            acc_s[nt][3] = (jg + 1 <= ig1) ? acc_s[nt][3] - slope * (float)(ig1 - jg - 1) : -1e30f;
        }

        // online softmax (quad reduce)
        float rm0 = -1e30f, rm1 = -1e30f;
        #pragma unroll
        for (int nt = 0; nt < 8; ++nt) {
            rm0 = fmaxf(rm0, fmaxf(acc_s[nt][0], acc_s[nt][1]));
            rm1 = fmaxf(rm1, fmaxf(acc_s[nt][2], acc_s[nt][3]));
        }
        rm0 = fmaxf(rm0, __shfl_xor_sync(0xffffffffu, rm0, 1));
        rm0 = fmaxf(rm0, __shfl_xor_sync(0xffffffffu, rm0, 2));
        rm1 = fmaxf(rm1, __shfl_xor_sync(0xffffffffu, rm1, 1));
        rm1 = fmaxf(rm1, __shfl_xor_sync(0xffffffffu, rm1, 2));
        float mn0 = fmaxf(m0r, rm0), mn1 = fmaxf(m1r, rm1);
        float al0 = __expf(m0r - mn0), al1 = __expf(m1r - mn1);
        float ls0 = 0.f, ls1 = 0.f;
        #pragma unroll
        for (int nt = 0; nt < 8; ++nt) {
            acc_s[nt][0] = __expf(acc_s[nt][0] - mn0);
            acc_s[nt][1] = __expf(acc_s[nt][1] - mn0);
            acc_s[nt][2] = __expf(acc_s[nt][2] - mn1);
            acc_s[nt][3] = __expf(acc_s[nt][3] - mn1);
            ls0 += acc_s[nt][0] + acc_s[nt][1];
            ls1 += acc_s[nt][2] + acc_s[nt][3];
        }
        ls0 += __shfl_xor_sync(0xffffffffu, ls0, 1);
        ls0 += __shfl_xor_sync(0xffffffffu, ls0, 2);
        ls1 += __shfl_xor_sync(0xffffffffu, ls1, 1);
        ls1 += __shfl_xor_sync(0xffffffffu, ls1, 2);
        l0r = l0r * al0 + ls0;  m0r = mn0;
        l1r = l1r * al1 + ls1;  m1r = mn1;
        #pragma unroll
        for (int nt = 0; nt < 8; ++nt) {
            acc_o[nt][0] *= al0; acc_o[nt][1] *= al0;
            acc_o[nt][2] *= al1; acc_o[nt][3] *= al1;
        }

        // stash P split as packed bf16 pairs (warp-private rows)
        #pragma unroll
        for (int nt = 0; nt < 8; ++nt) {
            uint32_t pb, ps;
            split2(acc_s[nt][0], acc_s[nt][1], pb, ps);
            Pb[(wr + lq) * AW + nt * 4 + lm] = pb;
            Ps[(wr + lq) * AW + nt * 4 + lm] = ps;
            split2(acc_s[nt][2], acc_s[nt][3], pb, ps);
            Pb[(wr + lq + 8) * AW + nt * 4 + lm] = pb;
            Ps[(wr + lq + 8) * AW + nt * 4 + lm] = ps;
        }
        __syncwarp();

        // O += P @ V (bf16x3: PbVb + PsVb + PbVs)
        #pragma unroll
        for (int ks = 0; ks < 4; ++ks) {
            int kc = ks * 8;
            uint32_t pa[4], psa[4];
            int ra = (wr + lq) * AW + kc + lm;
            int ra8 = (wr + lq + 8) * AW + kc + lm;
            pa[0] = Pb[ra];      pa[1] = Pb[ra8];
            pa[2] = Pb[ra + 4];  pa[3] = Pb[ra8 + 4];
            psa[0] = Ps[ra];     psa[1] = Ps[ra8];
            psa[2] = Ps[ra + 4]; psa[3] = Ps[ra8 + 4];
            #pragma unroll
            for (int nt = 0; nt < 8; ++nt) {
                int rb = (nt * 8 + lq) * AW + kc + lm;
                uint32_t vb_[2], vs_[2];
                vb_[0] = Vb[rb];     vb_[1] = Vb[rb + 4];
                vs_[0] = Vs[rb];     vs_[1] = Vs[rb + 4];
                mma_bf16(acc_o[nt], pa,  vb_);
                mma_bf16(acc_o[nt], psa, vb_);
                mma_bf16(acc_o[nt], pa,  vs_);
            }
        }
        __syncthreads();
    }

    // normalize, split, write packed pairs
    float inv0 = 1.f / l0r, inv1 = 1.f / l1r;
    uint32_t* obu = (uint32_t*)ob_g;
    uint32_t* osu = (uint32_t*)os_g;
    size_t base0 = (((size_t)b * NN + r0) * INNER + h * DH) >> 1;
    size_t base1 = (((size_t)b * NN + r0 + 8) * INNER + h * DH) >> 1;
    #pragma unroll
    for (int nt = 0; nt < 8; ++nt) {
        uint32_t pb, ps;
        split2(acc_o[nt][0] * inv0, acc_o[nt][1] * inv0, pb, ps);
        obu[base0 + nt * 4 + lm] = pb;
        osu[base0 + nt * 4 + lm] = ps;
        split2(acc_o[nt][2] * inv1, acc_o[nt][3] * inv1, pb, ps);
        obu[base1 + nt * 4 + lm] = pb;
        osu[base1 + nt * 4 + lm] = ps;
    }
}

extern "C" void kernel_launch(void* const* d_in, const int* in_sizes, int n_in,
                              void* d_out, int out_size) {
    const float* x     = (const float*)d_in[0];
    const float* gamma = (const float*)d_in[1];
    const float* beta  = (const float*)d_in[2];
    const float* wq1   = (const float*)d_in[3];
    const float* wqd   = (const float*)d_in[4];
    const float* wk1   = (const float*)d_in[5];
    const float* wkd   = (const float*)d_in[6];
    const float* wv1   = (const float*)d_in[7];
    const float* wvd   = (const float*)d_in[8];
    const float* wout  = (const float*)d_in[9];
    float* out = (float*)d_out;

    float* lin;
    __nv_bfloat16 *xnb, *xns, *wb, *ws, *qb, *qs, *kb, *ks, *vbT, *vsT, *ob, *os;
    cudaGetSymbolAddress((void**)&lin, g_lin);
    cudaGetSymbolAddress((void**)&xnb, g_xnb);  cudaGetSymbolAddress((void**)&xns, g_xns);
    cudaGetSymbolAddress((void**)&wb,  g_wb);   cudaGetSymbolAddress((void**)&ws,  g_ws);
    cudaGetSymbolAddress((void**)&qb,  g_qb);   cudaGetSymbolAddress((void**)&qs,  g_qs);
    cudaGetSymbolAddress((void**)&kb,  g_kb);   cudaGetSymbolAddress((void**)&ks,  g_ks);
    cudaGetSymbolAddress((void**)&vbT, g_vbT);  cudaGetSymbolAddress((void**)&vsT, g_vsT);
    cudaGetSymbolAddress((void**)&ob,  g_ob);   cudaGetSymbolAddress((void**)&os,  g_os);

    cudaFuncSetAttribute(gemm_bf16, cudaFuncAttributeMaxDynamicSharedMemorySize, SM_GEMM);
    cudaFuncSetAttribute(attn_kernel, cudaFuncAttributeMaxDynamicSharedMemorySize, SMEM_ATTN);

    // 1) LayerNorm (split bf16 out) + weight split
    ln_kernel<<<ROWS, 256>>>(x, gamma, beta, xnb, xns);
    wsplit_kernel<<<(4 * WSZ) / 256, 256>>>(wq1, wk1, wv1, wout, wb, ws);

    // 2) q/k/v pointwise projections (bf16x3, one launch, z=3) -> lin fp32
    dim3 g1(4, 32, 3);
    gemm_bf16<<<g1, 256, SM_GEMM>>>(xnb, xns, wb, ws, WSZ, lin, (size_t)ROWS * INNER);

    // 3) depthwise conv + split (q/k d-major, v transposed n-major)
    conv_qk<<<(ROWS * INNER) / 256, 256>>>(lin, wqd, wkd, qb, qs, kb, ks);
    conv_v<<<dim3(NN / 32, INNER / 32, BB), 256>>>(lin + 2 * (size_t)ROWS * INNER, wvd, vbT, vsT);

    // 4) flash attention (bf16x3) -> split bf16 out
    attn_kernel<<<dim3(NN / 64, BB * HH), 128, SMEM_ATTN>>>(qb, qs, kb, ks, vbT, vsT, ob, os);

    // 5) output projection (bf16x3) straight into d_out
    dim3 g2(4, 32, 1);
    gemm_bf16<<<g2, 256, SM_GEMM>>>(ob, os, wb + 3 * WSZ, ws + 3 * WSZ, 0, out, 0);
}